// round 7
// baseline (speedup 1.0000x reference)
#include <cuda_runtime.h>

#define DIM 16
typedef unsigned long long ull;

// ---------- packed f32x2 helpers ----------
__device__ __forceinline__ ull pk2(float lo, float hi){
    ull r; asm("mov.b64 %0, {%1, %2};" : "=l"(r) : "f"(lo), "f"(hi)); return r;
}
__device__ __forceinline__ ull dup2(float v){ return pk2(v, v); }
__device__ __forceinline__ ull fma2(ull a, ull b, ull c){
    ull d; asm("fma.rn.f32x2 %0, %1, %2, %3;" : "=l"(d) : "l"(a), "l"(b), "l"(c)); return d;
}
__device__ __forceinline__ ull mul2(ull a, ull b){
    ull d; asm("mul.rn.f32x2 %0, %1, %2;" : "=l"(d) : "l"(a), "l"(b)); return d;
}
__device__ __forceinline__ ull swp(ull v){
    unsigned lo, hi; asm("mov.b64 {%0, %1}, %2;" : "=r"(lo), "=r"(hi) : "l"(v));
    ull r; asm("mov.b64 %0, {%1, %2};" : "=l"(r) : "r"(hi), "r"(lo)); return r;
}
__device__ __forceinline__ void unpk(ull v, float& lo, float& hi){
    asm("mov.b64 {%0, %1}, %2;" : "=f"(lo), "=f"(hi) : "l"(v));
}

// ---------- scalar complex helpers (prologue) ----------
__device__ __forceinline__ float2 cmul(float2 a, float2 b){
    return make_float2(fmaf(a.x, b.x, -a.y * b.y),
                       fmaf(a.x, b.y,  a.y * b.x));
}
__device__ __forceinline__ float2 cmadd(float2 a, float2 b, float2 acc){
    acc.x = fmaf(a.x, b.x, fmaf(-a.y, b.y, acc.x));
    acc.y = fmaf(a.x, b.y, fmaf( a.y, b.x, acc.y));
    return acc;
}
__device__ __forceinline__ void mm2(const float2* A, const float2* B, float2* C){
    C[0] = cmadd(A[1], B[2], cmul(A[0], B[0]));
    C[1] = cmadd(A[1], B[3], cmul(A[0], B[1]));
    C[2] = cmadd(A[3], B[2], cmul(A[2], B[0]));
    C[3] = cmadd(A[3], B[3], cmul(A[2], B[1]));
}

// state update for one qubit gate, scalars (G00, G01), SU(2) implied rest.
// i is a compile-time constant under full unrolling.
__device__ __forceinline__ void apply_gate(ull* Rr, ull* Ii, const int i,
                                           float g00x, float g00y,
                                           float g01x, float g01y)
{
    if (i < 3){
        ull pG00x  = dup2( g00x), pG00y  = dup2( g00y);
        ull pnG00y = dup2(-g00y);
        ull pG01x  = dup2( g01x), pnG01x = dup2(-g01x);
        ull pG01y  = dup2( g01y), pnG01y = dup2(-g01y);
        const int hs = 4 >> i;   // slot stride
        #pragma unroll
        for (int m = 0; m < 8; m++){
            if (m & hs) continue;
            const int u = m, v = m + hs;
            ull R0 = Rr[u], I0 = Ii[u], R1 = Rr[v], I1 = Ii[v];
            Rr[u] = fma2(pnG01y,I1, fma2(pG01x ,R1, fma2(pnG00y,I0, mul2(pG00x ,R0))));
            Ii[u] = fma2(pG01x ,I1, fma2(pG01y ,R1, fma2(pG00x ,I0, mul2(pG00y ,R0))));
            Rr[v] = fma2(pG00y ,I1, fma2(pG00x ,R1, fma2(pnG01y,I0, mul2(pnG01x,R0))));
            Ii[v] = fma2(pG00x ,I1, fma2(pnG00y,R1, fma2(pnG01x,I0, mul2(pG01y ,R0))));
        }
    } else {
        // qubit 3 (stride 1): partners share a packed register -> swaps
        ull c1  = dup2( g00x);
        ull c2v = pk2( g01x, -g01x);
        ull c3  = pk2(-g00y,  g00y);
        ull c4  = dup2(-g01y);
        ull c5  = pk2( g00y, -g00y);
        ull c6  = dup2( g01y);
        #pragma unroll
        for (int m = 0; m < 8; m++){
            ull R = Rr[m], I = Ii[m];
            ull Rs = swp(R), Is = swp(I);
            Rr[m] = fma2(c4, Is, fma2(c3, I, fma2(c2v, Rs, mul2(c1, R))));
            Ii[m] = fma2(c6, Rs, fma2(c5, R, fma2(c2v, Is, mul2(c1, I))));
        }
    }
}

__global__ void __launch_bounds__(256) vqc_fused(
    const float4* __restrict__ x, const float* __restrict__ theta,
    const float* __restrict__ lmbd, float4* __restrict__ out, int B)
{
    __shared__ float2 sT[4][4][4];    // folded Rz*Ry*Rx per (theta-layer, qubit)
    __shared__ float2 sP[3][4][2];    // top row (00,01) of P_l,i (SU(2))
    __shared__ ull    sPpk[3][2][7];  // packed-over-qubit-pair P comps (+negated)
    __shared__ float2 sPsi0[DIM];     // CZ * T0 |0>
    __shared__ float  sL[12];

    const int t = threadIdx.x;

    // ---- prologue stage 1: the 16 theta-gates T[l][i] (fast trig: err ~1e-6) ----
    if (t < 16){
        int l = t >> 2, i = t & 3;
        float t0 = theta[t*3 + 0], t1 = theta[t*3 + 1], t2 = theta[t*3 + 2];
        float cx, sx, cy, sy, cz, sz;
        __sincosf(0.5f*t0, &sx, &cx);
        __sincosf(0.5f*t1, &sy, &cy);
        __sincosf(0.5f*t2, &sz, &cz);
        float2 RX[4] = {{cx,0.f},{0.f,-sx},{0.f,-sx},{cx,0.f}};
        float2 RY[4] = {{cy,0.f},{-sy,0.f},{sy,0.f},{cy,0.f}};
        float2 RZ[4] = {{cz,-sz},{0.f,0.f},{0.f,0.f},{cz,sz}};
        float2 YX[4], M[4];
        mm2(RY, RX, YX);
        mm2(RZ, YX, M);
        #pragma unroll
        for (int e = 0; e < 4; e++) sT[l][i][e] = M[e];
    }
    if (t >= 32 && t < 44) sL[t - 32] = lmbd[t - 32];
    __syncthreads();

    // ---- prologue stage 2: fold P_l (top row) + psi0 ----
    if (t < 12){
        int l = t >> 2, i = t & 3;
        float2 G0, G1;
        if (l < 2){
            G0 = cmadd(sT[l+1][i][1], sT[3][i][2], cmul(sT[l+1][i][0], sT[3][i][0]));
            G1 = cmadd(sT[l+1][i][1], sT[3][i][3], cmul(sT[l+1][i][0], sT[3][i][1]));
        } else {
            G0 = sT[3][i][0];
            G1 = sT[3][i][1];
        }
        sP[l][i][0] = G0;
        sP[l][i][1] = G1;
    }
    if (t >= 16 && t < 32){
        int s = t - 16;
        float2 v = make_float2(1.f, 0.f);
        #pragma unroll
        for (int i = 0; i < 4; i++){
            int bi = (s >> (3 - i)) & 1;
            v = cmul(v, sT[0][i][bi*2 + 0]);
        }
        int b0=(s>>3)&1, b1=(s>>2)&1, b2=(s>>1)&1, b3=s&1;
        int e = (b0&b1) ^ (b1&b2) ^ (b2&b3) ^ (b0&b3);
        if (e) { v.x = -v.x; v.y = -v.y; }
        sPsi0[s] = v;
    }
    __syncthreads();

    // ---- prologue stage 3: pack P over qubit pairs with pre-negated comps ----
    if (t < 6){
        int l = t >> 1, p = t & 1;
        float2 A0 = sP[l][2*p][0],  B0 = sP[l][2*p+1][0];   // P00 of (q_lo, q_hi)
        float2 A1 = sP[l][2*p][1],  B1 = sP[l][2*p+1][1];   // P01
        sPpk[l][p][0] = pk2( A0.x,  B0.x);   // P00x
        sPpk[l][p][1] = pk2( A0.y,  B0.y);   // P00y
        sPpk[l][p][2] = pk2(-A0.y, -B0.y);   // -P00y
        sPpk[l][p][3] = pk2( A1.x,  B1.x);   // P01x
        sPpk[l][p][4] = pk2(-A1.x, -B1.x);   // -P01x
        sPpk[l][p][5] = pk2( A1.y,  B1.y);   // P01y
        sPpk[l][p][6] = pk2(-A1.y, -B1.y);   // -P01y
    }
    __syncthreads();

    // ---- main per-element circuit ----
    int b = blockIdx.x * blockDim.x + t;
    if (b >= B) return;

    float4 xv = x[b];
    float xq[4] = {xv.x, xv.y, xv.z, xv.w};

    // R[m] = (re_{2m}, re_{2m+1}),  I[m] = (im_{2m}, im_{2m+1})
    ull Rr[8], Ii[8];
    #pragma unroll
    for (int m = 0; m < 8; m++){
        float2 a = sPsi0[2*m], c = sPsi0[2*m+1];
        Rr[m] = pk2(a.x, c.x);
        Ii[m] = pk2(a.y, c.y);
    }

    #pragma unroll
    for (int l = 0; l < 3; l++){
        float ch[4], sh[4];
        #pragma unroll
        for (int i = 0; i < 4; i++){
            float a = sL[l*4 + i] * xq[i];
            __sincosf(0.5f * a, &sh[i], &ch[i]);
        }
        #pragma unroll
        for (int p = 0; p < 2; p++){
            // z-angle: pair0 -> a0 trig (ch[0]); pair1 -> a1 trig (ch[1])
            float cz = ch[p], sz = sh[p];
            // packed build of G for qubits (2p, 2p+1); lanes = (lo=2p, hi=2p+1)
            ull ci = pk2(ch[2*p], ch[2*p+1]);
            ull si = pk2(sh[2*p], sh[2*p+1]);
            ull c2 = mul2(ci, ci), s2 = mul2(si, si), sc = mul2(si, ci);
            ull dcz = dup2(cz), dsz = dup2(sz), dnsz = dup2(-sz);
            ull dnczsz = dup2(-(cz + sz)), dszmcz = dup2(sz - cz);
            // M = Rz*Ry*Rx (top row): M00 = (cz*c2+sz*s2, cz*s2-sz*c2)
            //                         M01 = (-sc*(cz+sz), sc*(sz-cz))
            ull M00re = fma2(dcz, c2, mul2(dsz, s2));
            ull M00im = fma2(dcz, s2, mul2(dnsz, c2));
            ull M01re = mul2(sc, dnczsz);
            ull M01im = mul2(sc, dszmcz);
            // G = P*M (top row), packed; M10=(-M01x,M01y), M11=(M00x,-M00y)
            ull P00x  = sPpk[l][p][0], P00y  = sPpk[l][p][1], nP00y = sPpk[l][p][2];
            ull P01x  = sPpk[l][p][3], nP01x = sPpk[l][p][4];
            ull P01y  = sPpk[l][p][5], nP01y = sPpk[l][p][6];
            ull G00re = fma2(nP01y, M01im, fma2(nP01x, M01re, fma2(nP00y, M00im, mul2(P00x, M00re))));
            ull G00im = fma2(nP01y, M01re, fma2(P01x , M01im, fma2(P00y , M00re, mul2(P00x, M00im))));
            ull G01re = fma2(P01y , M00im, fma2(P01x , M00re, fma2(nP00y, M01im, mul2(P00x, M01re))));
            ull G01im = fma2(P01y , M00re, fma2(nP01x, M00im, fma2(P00y , M01re, mul2(P00x, M01im))));
            // extract per-qubit scalars and apply
            float g00x0, g00x1, g00y0, g00y1, g01x0, g01x1, g01y0, g01y1;
            unpk(G00re, g00x0, g00x1);
            unpk(G00im, g00y0, g00y1);
            unpk(G01re, g01x0, g01x1);
            unpk(G01im, g01y0, g01y1);
            apply_gate(Rr, Ii, 2*p,     g00x0, g00y0, g01x0, g01y0);
            apply_gate(Rr, Ii, 2*p + 1, g00x1, g00y1, g01x1, g01y1);
        }
        if (l < 2){
            // CZ: flip states 3 (slot1 hi), 6 (slot3 lo), 9 (slot4 hi), 12 (slot6 lo)
            const ull HI = 0x8000000000000000ull, LO = 0x80000000ull;
            Rr[1] ^= HI; Ii[1] ^= HI;
            Rr[3] ^= LO; Ii[3] ^= LO;
            Rr[4] ^= HI; Ii[4] ^= HI;
            Rr[6] ^= LO; Ii[6] ^= LO;
        }
    }

    // probs + Walsh-tree reduction (consume packed pairs immediately)
    float d3 = 0.f;
    float e[8];
    #pragma unroll
    for (int m = 0; m < 8; m++){
        ull q = fma2(Ii[m], Ii[m], mul2(Rr[m], Rr[m]));
        float plo, phi; unpk(q, plo, phi);
        d3 += (plo - phi);
        e[m] = plo + phi;
    }
    float d2 = (e[0]-e[1]) + (e[2]-e[3]) + (e[4]-e[5]) + (e[6]-e[7]);
    float f0 = e[0]+e[1], f1 = e[2]+e[3], f2 = e[4]+e[5], f3 = e[6]+e[7];
    float d1 = (f0-f1) + (f2-f3);
    float o0 = (f0 + f1) - (f2 + f3);

    out[b] = make_float4(o0, d1, d2, d3);
}

extern "C" void kernel_launch(void* const* d_in, const int* in_sizes, int n_in,
                              void* d_out, int out_size)
{
    const float* x     = (const float*)d_in[0];
    const float* theta = (const float*)d_in[1];
    const float* lmbd  = (const float*)d_in[2];
    int B = in_sizes[0] / 4;

    vqc_fused<<<(B + 255) / 256, 256>>>((const float4*)x, theta, lmbd,
                                        (float4*)d_out, B);
}